// round 1
// baseline (speedup 1.0000x reference)
#include <cuda_runtime.h>

// Problem constants
#define C_EMBD 1024
#define NHEAD  16
#define HD     64
#define BATCH  4
#define SEQ    2048
#define M_TOT  (BATCH * SEQ)        // 8192
#define N_QKV  (3 * C_EMBD)         // 3072

// Scratch (device globals; allocation inside kernel_launch is forbidden)
__device__ float g_q[BATCH * NHEAD * SEQ * HD];   // [bh][t][d]
__device__ float g_k[BATCH * NHEAD * SEQ * HD];
__device__ float g_v[BATCH * NHEAD * SEQ * HD];
__device__ float g_y[M_TOT * C_EMBD];             // [b*T + t][h*64 + d]

// ---------------------------------------------------------------------------
// GEMM 1: qkv = x @ W_attn + b_attn, scattered into g_q/g_k/g_v
// M=8192, K=1024, N=3072. BM=BN=64, BK=16, 256 threads, 4x4 micro-tile.
// Each block's 64-wide N slice lies entirely inside one (which, head) chunk.
// ---------------------------------------------------------------------------
__global__ __launch_bounds__(256) void gemm_qkv(const float* __restrict__ A,
                                                const float* __restrict__ W,
                                                const float* __restrict__ bias) {
    __shared__ float As[16][64];   // [k][m]
    __shared__ float Bs[16][64];   // [k][n]

    const int bm = blockIdx.y * 64;
    const int bn = blockIdx.x * 64;
    const int tid = threadIdx.x;
    const int tx = tid % 16;       // n micro
    const int ty = tid / 16;       // m micro

    // load mappings
    const int a_row = tid / 4;            // 0..63
    const int a_k4  = (tid % 4) * 4;      // 0,4,8,12
    const int b_row = tid / 16;           // 0..15
    const int b_col = (tid % 16) * 4;     // 0..60

    float acc[4][4] = {};

    for (int k0 = 0; k0 < C_EMBD; k0 += 16) {
        float4 av = *(const float4*)&A[(size_t)(bm + a_row) * C_EMBD + k0 + a_k4];
        As[a_k4 + 0][a_row] = av.x;
        As[a_k4 + 1][a_row] = av.y;
        As[a_k4 + 2][a_row] = av.z;
        As[a_k4 + 3][a_row] = av.w;
        *(float4*)&Bs[b_row][b_col] =
            *(const float4*)&W[(size_t)(k0 + b_row) * N_QKV + bn + b_col];
        __syncthreads();

        #pragma unroll
        for (int k = 0; k < 16; k++) {
            float4 af = *(const float4*)&As[k][ty * 4];
            float4 bf = *(const float4*)&Bs[k][tx * 4];
            float a0 = af.x, a1 = af.y, a2 = af.z, a3 = af.w;
            acc[0][0] += a0 * bf.x; acc[0][1] += a0 * bf.y; acc[0][2] += a0 * bf.z; acc[0][3] += a0 * bf.w;
            acc[1][0] += a1 * bf.x; acc[1][1] += a1 * bf.y; acc[1][2] += a1 * bf.z; acc[1][3] += a1 * bf.w;
            acc[2][0] += a2 * bf.x; acc[2][1] += a2 * bf.y; acc[2][2] += a2 * bf.z; acc[2][3] += a2 * bf.w;
            acc[3][0] += a3 * bf.x; acc[3][1] += a3 * bf.y; acc[3][2] += a3 * bf.z; acc[3][3] += a3 * bf.w;
        }
        __syncthreads();
    }

    // Epilogue: bias + scatter. This block's 64 columns = one (which, head) slice.
    const int which = bn / C_EMBD;              // 0=q 1=k 2=v
    const int head  = (bn % C_EMBD) / HD;
    float* dst = (which == 0) ? g_q : (which == 1) ? g_k : g_v;
    float4 bv = *(const float4*)&bias[bn + tx * 4];

    #pragma unroll
    for (int i = 0; i < 4; i++) {
        int m = bm + ty * 4 + i;
        int b = m / SEQ, t = m % SEQ;
        float4 o;
        o.x = acc[i][0] + bv.x;
        o.y = acc[i][1] + bv.y;
        o.z = acc[i][2] + bv.z;
        o.w = acc[i][3] + bv.w;
        *(float4*)&dst[((size_t)(b * NHEAD + head) * SEQ + t) * HD + tx * 4] = o;
    }
}

// ---------------------------------------------------------------------------
// Flash attention, fp32, online softmax. 128 queries/block, 1 query/thread.
// K/V tiles (64 keys x 64 dims, 32KB) in shared; q row + output acc in regs.
// Long blocks (high q tiles) launched first to reduce tail imbalance.
// ---------------------------------------------------------------------------
__global__ __launch_bounds__(128, 3) void attn_kernel() {
    const int bh  = blockIdx.y;
    const int qt  = (gridDim.x - 1) - blockIdx.x;     // reverse: long blocks first
    const int q0  = qt * 128;
    const int tid = threadIdx.x;
    const int qi  = q0 + tid;

    __shared__ float Ks[64][64];
    __shared__ float Vs[64][64];

    const float* qp = &g_q[((size_t)bh * SEQ + qi) * HD];
    float qr[64];
    #pragma unroll
    for (int i = 0; i < 16; i++) {
        float4 v = *(const float4*)&qp[i * 4];
        qr[i * 4 + 0] = v.x; qr[i * 4 + 1] = v.y;
        qr[i * 4 + 2] = v.z; qr[i * 4 + 3] = v.w;
    }

    float mx = -1e30f, l = 0.0f;
    float acc[64];
    #pragma unroll
    for (int d = 0; d < 64; d++) acc[d] = 0.0f;

    const int ntiles = qt * 2 + 2;    // keys up to q0+127
    const int r = tid >> 1;
    const int half = (tid & 1) * 32;

    for (int kb = 0; kb < ntiles; kb++) {
        const int j0 = kb * 64;
        {
            const float* kp = &g_k[((size_t)bh * SEQ + j0 + r) * HD + half];
            const float* vp = &g_v[((size_t)bh * SEQ + j0 + r) * HD + half];
            #pragma unroll
            for (int i = 0; i < 8; i++) {
                *(float4*)&Ks[r][half + i * 4] = *(const float4*)&kp[i * 4];
                *(float4*)&Vs[r][half + i * 4] = *(const float4*)&vp[i * 4];
            }
        }
        __syncthreads();

        int jmax = qi - j0 + 1;
        if (jmax > 64) jmax = 64;
        for (int j = 0; j < jmax; j++) {
            float s = 0.0f;
            #pragma unroll
            for (int d4 = 0; d4 < 16; d4++) {
                float4 kv = *(const float4*)&Ks[j][d4 * 4];
                s += qr[d4 * 4 + 0] * kv.x + qr[d4 * 4 + 1] * kv.y
                   + qr[d4 * 4 + 2] * kv.z + qr[d4 * 4 + 3] * kv.w;
            }
            s *= 0.125f;   // 1/sqrt(64)

            if (s > mx) {
                float corr = __expf(mx - s);
                l *= corr;
                #pragma unroll
                for (int d = 0; d < 64; d++) acc[d] *= corr;
                mx = s;
            }
            float p = __expf(s - mx);
            l += p;
            #pragma unroll
            for (int d4 = 0; d4 < 16; d4++) {
                float4 vv = *(const float4*)&Vs[j][d4 * 4];
                acc[d4 * 4 + 0] += p * vv.x;
                acc[d4 * 4 + 1] += p * vv.y;
                acc[d4 * 4 + 2] += p * vv.z;
                acc[d4 * 4 + 3] += p * vv.w;
            }
        }
        __syncthreads();
    }

    const float inv = 1.0f / l;
    const int b = bh >> 4, h = bh & 15;
    float* yp = &g_y[((size_t)b * SEQ + qi) * C_EMBD + h * HD];
    #pragma unroll
    for (int d4 = 0; d4 < 16; d4++) {
        float4 o;
        o.x = acc[d4 * 4 + 0] * inv;
        o.y = acc[d4 * 4 + 1] * inv;
        o.z = acc[d4 * 4 + 2] * inv;
        o.w = acc[d4 * 4 + 3] * inv;
        *(float4*)&yp[d4 * 4] = o;
    }
}

// ---------------------------------------------------------------------------
// GEMM 2: out = y @ W_proj + b_proj. M=8192, K=1024, N=1024.
// ---------------------------------------------------------------------------
__global__ __launch_bounds__(256) void gemm_proj(const float* __restrict__ W,
                                                 const float* __restrict__ bias,
                                                 float* __restrict__ out) {
    __shared__ float As[16][64];
    __shared__ float Bs[16][64];

    const int bm = blockIdx.y * 64;
    const int bn = blockIdx.x * 64;
    const int tid = threadIdx.x;
    const int tx = tid % 16;
    const int ty = tid / 16;

    const int a_row = tid / 4;
    const int a_k4  = (tid % 4) * 4;
    const int b_row = tid / 16;
    const int b_col = (tid % 16) * 4;

    float acc[4][4] = {};

    for (int k0 = 0; k0 < C_EMBD; k0 += 16) {
        float4 av = *(const float4*)&g_y[(size_t)(bm + a_row) * C_EMBD + k0 + a_k4];
        As[a_k4 + 0][a_row] = av.x;
        As[a_k4 + 1][a_row] = av.y;
        As[a_k4 + 2][a_row] = av.z;
        As[a_k4 + 3][a_row] = av.w;
        *(float4*)&Bs[b_row][b_col] =
            *(const float4*)&W[(size_t)(k0 + b_row) * C_EMBD + bn + b_col];
        __syncthreads();

        #pragma unroll
        for (int k = 0; k < 16; k++) {
            float4 af = *(const float4*)&As[k][ty * 4];
            float4 bf = *(const float4*)&Bs[k][tx * 4];
            float a0 = af.x, a1 = af.y, a2 = af.z, a3 = af.w;
            acc[0][0] += a0 * bf.x; acc[0][1] += a0 * bf.y; acc[0][2] += a0 * bf.z; acc[0][3] += a0 * bf.w;
            acc[1][0] += a1 * bf.x; acc[1][1] += a1 * bf.y; acc[1][2] += a1 * bf.z; acc[1][3] += a1 * bf.w;
            acc[2][0] += a2 * bf.x; acc[2][1] += a2 * bf.y; acc[2][2] += a2 * bf.z; acc[2][3] += a2 * bf.w;
            acc[3][0] += a3 * bf.x; acc[3][1] += a3 * bf.y; acc[3][2] += a3 * bf.z; acc[3][3] += a3 * bf.w;
        }
        __syncthreads();
    }

    float4 bv = *(const float4*)&bias[bn + tx * 4];
    #pragma unroll
    for (int i = 0; i < 4; i++) {
        int m = bm + ty * 4 + i;
        float4 o;
        o.x = acc[i][0] + bv.x;
        o.y = acc[i][1] + bv.y;
        o.z = acc[i][2] + bv.z;
        o.w = acc[i][3] + bv.w;
        *(float4*)&out[(size_t)m * C_EMBD + bn + tx * 4] = o;
    }
}

extern "C" void kernel_launch(void* const* d_in, const int* in_sizes, int n_in,
                              void* d_out, int out_size) {
    const float* x      = (const float*)d_in[0];
    const float* W_attn = (const float*)d_in[1];
    const float* b_attn = (const float*)d_in[2];
    const float* W_proj = (const float*)d_in[3];
    const float* b_proj = (const float*)d_in[4];
    float* out = (float*)d_out;

    gemm_qkv<<<dim3(N_QKV / 64, M_TOT / 64), 256>>>(x, W_attn, b_attn);
    attn_kernel<<<dim3(SEQ / 128, BATCH * NHEAD), 128>>>();
    gemm_proj<<<dim3(C_EMBD / 64, M_TOT / 64), 256>>>(W_proj, b_proj, out);
}

// round 5
// speedup vs baseline: 1.3037x; 1.3037x over previous
#include <cuda_runtime.h>
#include <cuda_bf16.h>
#include <mma.h>
#include <cstdint>

using namespace nvcuda;

// Problem constants
#define C_EMBD 1024
#define NHEAD  16
#define HD     64
#define BATCH  4
#define SEQ    2048
#define M_TOT  8192
#define N_QKV  3072
#define KDIM   1024

// fp32 scratch
__device__ float g_q[BATCH * NHEAD * SEQ * HD];
__device__ float g_k[BATCH * NHEAD * SEQ * HD];
__device__ float g_v[BATCH * NHEAD * SEQ * HD];
__device__ float g_y[M_TOT * C_EMBD];
// bf16 hi/lo scratch (16B aligned for vectorized access)
__device__ __align__(16) __nv_bfloat16 g_xh[M_TOT * KDIM],   g_xl[M_TOT * KDIM];
__device__ __align__(16) __nv_bfloat16 g_wah[KDIM * N_QKV],  g_wal[KDIM * N_QKV];   // [K][N] row-major
__device__ __align__(16) __nv_bfloat16 g_wph[KDIM * C_EMBD], g_wpl[KDIM * C_EMBD];  // [K][N] row-major
__device__ __align__(16) __nv_bfloat16 g_yh[M_TOT * KDIM],   g_yl[M_TOT * KDIM];

// tensor-path-alive flag (written by canary every call — deterministic)
__device__ int g_ok;

// ---------------------------------------------------------------------------
// hi/lo split helpers
// ---------------------------------------------------------------------------
__device__ __forceinline__ uint32_t pack2(float lo, float hi) {
    uint32_t r;
    asm("cvt.rn.bf16x2.f32 %0, %1, %2;" : "=r"(r) : "f"(hi), "f"(lo));
    return r;
}
__device__ __forceinline__ void split2(float f0, float f1, uint32_t& hi, uint32_t& lo) {
    hi = pack2(f0, f1);
    float h0 = __uint_as_float(hi << 16);
    float h1 = __uint_as_float(hi & 0xffff0000u);
    lo = pack2(f0 - h0, f1 - h1);
}

// ---------------------------------------------------------------------------
// Canary: does bf16 wmma produce real results on this part?
// All-ones 16x16x16 -> every C element must be 16.
// ---------------------------------------------------------------------------
__global__ void canary_kernel() {
    wmma::fragment<wmma::matrix_a, 16, 16, 16, __nv_bfloat16, wmma::row_major> a;
    wmma::fragment<wmma::matrix_b, 16, 16, 16, __nv_bfloat16, wmma::row_major> b;
    wmma::fragment<wmma::accumulator, 16, 16, 16, float> c;
    wmma::fill_fragment(a, __float2bfloat16(1.0f));
    wmma::fill_fragment(b, __float2bfloat16(1.0f));
    wmma::fill_fragment(c, 0.0f);
    wmma::mma_sync(c, a, b, c);
    __shared__ float buf[256];
    wmma::store_matrix_sync(buf, c, 16, wmma::mem_row_major);
    __syncwarp();
    if (threadIdx.x == 0) {
        bool ok = true;
        for (int i = 0; i < 256; i += 17)
            if (fabsf(buf[i] - 16.0f) > 0.5f) ok = false;
        g_ok = ok ? 1 : 0;
    }
}

// ---------------------------------------------------------------------------
// Convert fp32 -> bf16 hi/lo (elementwise, layout preserved). Gated on g_ok.
// sel: 0=x, 1=W_attn, 2=W_proj, 3=g_y
// ---------------------------------------------------------------------------
__global__ __launch_bounds__(256) void cvt_gate(const float* __restrict__ src, int sel, int n4) {
    if (!g_ok) return;
    int i = blockIdx.x * 256 + threadIdx.x;
    if (i >= n4) return;
    const float4* s4 = (const float4*)((sel == 3) ? (const float*)g_y : src);
    __nv_bfloat16 *dh, *dl;
    if (sel == 0)      { dh = g_xh;  dl = g_xl;  }
    else if (sel == 1) { dh = g_wah; dl = g_wal; }
    else if (sel == 2) { dh = g_wph; dl = g_wpl; }
    else               { dh = g_yh;  dl = g_yl;  }
    float4 v = s4[i];
    uint32_t h0, l0, h1, l1;
    split2(v.x, v.y, h0, l0);
    split2(v.z, v.w, h1, l1);
    ((uint2*)dh)[i] = make_uint2(h0, h1);
    ((uint2*)dl)[i] = make_uint2(l0, l1);
}

// ---------------------------------------------------------------------------
// wmma bf16 hi/lo 3-term GEMM. C[128x128] = A[128xK]*B[Kx128] + bias.
// 256 threads = 8 warps (2m x 4n), warp tile 64x32 (4x2 frags of 16x16).
// A from (hi,lo) [M][K] bf16 row-major; B from (hi,lo) [K][N] bf16 row-major.
// acc initialized from bias-replicated tile; D += Ah*Bh + Ah*Bl + Al*Bh.
// EPI 0 = qkv scatter (N=3072), EPI 1 = store to out (N=1024).
// Gated: runs only if g_ok == 1.
// ---------------------------------------------------------------------------
template <int EPI>
__global__ __launch_bounds__(256) void gemm_wmma(float* __restrict__ out,
                                                 const float* __restrict__ bias) {
    if (!g_ok) return;
    constexpr int N = (EPI == 0) ? N_QKV : C_EMBD;

    __shared__ __nv_bfloat16 AsH[128 * 24], AsL[128 * 24];
    __shared__ __nv_bfloat16 BsH[16 * 136], BsL[16 * 136];
    __shared__ float sbias[16 * 132];

    const int bm = blockIdx.y * 128;
    const int bn = blockIdx.x * 128;
    const int tid = threadIdx.x;
    const int wid = tid >> 5;
    const int wm = (wid >> 2) * 64;
    const int wn = (wid & 3) * 32;

    const uint4* Ah4 = (const uint4*)((EPI == 0) ? g_xh : g_yh);
    const uint4* Al4 = (const uint4*)((EPI == 0) ? g_xl : g_yl);
    const uint4* Bh4 = (const uint4*)((EPI == 0) ? g_wah : g_wph);
    const uint4* Bl4 = (const uint4*)((EPI == 0) ? g_wal : g_wpl);

    // load mappings: A tile 128 rows x 2 uint4; B tile 16 rows x 16 uint4
    const int arow = tid >> 1, aseg = tid & 1;
    const int krow = tid >> 4, bseg = tid & 15;

    uint4 pAh, pAl, pBh, pBl;
    auto loadG = [&](int t) {
        size_t ia = (size_t)(bm + arow) * (KDIM / 8) + t * 2 + aseg;
        pAh = Ah4[ia];
        pAl = Al4[ia];
        size_t ib = (size_t)(t * 16 + krow) * (N / 8) + (bn >> 3) + bseg;
        pBh = Bh4[ib];
        pBl = Bl4[ib];
    };
    auto storeS = [&]() {
        *(uint4*)&AsH[arow * 24 + aseg * 8] = pAh;
        *(uint4*)&AsL[arow * 24 + aseg * 8] = pAl;
        *(uint4*)&BsH[krow * 136 + bseg * 8] = pBh;
        *(uint4*)&BsL[krow * 136 + bseg * 8] = pBl;
    };

    // bias replicated tile: 16 identical rows of this block's 128 bias values
    {
        int br = tid >> 4, bc = (tid & 15) * 8;
        float4 b0 = *(const float4*)&bias[bn + bc];
        float4 b1 = *(const float4*)&bias[bn + bc + 4];
        *(float4*)&sbias[br * 132 + bc] = b0;
        *(float4*)&sbias[br * 132 + bc + 4] = b1;
    }

    wmma::fragment<wmma::accumulator, 16, 16, 16, float> acc[4][2];

    loadG(0);
    storeS();
    __syncthreads();

    // init acc = bias
    #pragma unroll
    for (int i = 0; i < 4; i++)
        #pragma unroll
        for (int j = 0; j < 2; j++)
            wmma::load_matrix_sync(acc[i][j], &sbias[wn + j * 16], 132, wmma::mem_row_major);

    const int ntiles = KDIM / 16;
    for (int t = 0; t < ntiles; t++) {
        if (t + 1 < ntiles) loadG(t + 1);

        wmma::fragment<wmma::matrix_a, 16, 16, 16, __nv_bfloat16, wmma::row_major> aH[4], aL[4];
        wmma::fragment<wmma::matrix_b, 16, 16, 16, __nv_bfloat16, wmma::row_major> bH[2], bL[2];
        #pragma unroll
        for (int i = 0; i < 4; i++) {
            wmma::load_matrix_sync(aH[i], &AsH[(wm + i * 16) * 24], 24);
            wmma::load_matrix_sync(aL[i], &AsL[(wm + i * 16) * 24], 24);
        }
        #pragma unroll
        for (int j = 0; j < 2; j++) {
            wmma::load_matrix_sync(bH[j], &BsH[wn + j * 16], 136);
            wmma::load_matrix_sync(bL[j], &BsL[wn + j * 16], 136);
        }
        #pragma unroll
        for (int i = 0; i < 4; i++)
            #pragma unroll
            for (int j = 0; j < 2; j++) {
                wmma::mma_sync(acc[i][j], aH[i], bH[j], acc[i][j]);
                wmma::mma_sync(acc[i][j], aH[i], bL[j], acc[i][j]);
                wmma::mma_sync(acc[i][j], aL[i], bH[j], acc[i][j]);
            }

        __syncthreads();
        if (t + 1 < ntiles) {
            storeS();
            __syncthreads();
        }
    }

    // Epilogue: store fragments straight to their destinations
    #pragma unroll
    for (int i = 0; i < 4; i++) {
        #pragma unroll
        for (int j = 0; j < 2; j++) {
            int m0 = bm + wm + i * 16;
            int gn = bn + wn + j * 16;
            if (EPI == 0) {
                int which = gn >> 10;
                int head = (gn >> 6) & 15;
                int d0 = gn & 63;
                float* dst = (which == 0) ? g_q : (which == 1) ? g_k : g_v;
                int b = m0 >> 11, t0 = m0 & 2047;
                wmma::store_matrix_sync(
                    &dst[((size_t)(b * NHEAD + head) * SEQ + t0) * HD + d0],
                    acc[i][j], HD, wmma::mem_row_major);
            } else {
                wmma::store_matrix_sync(&out[(size_t)m0 * C_EMBD + gn],
                                        acc[i][j], C_EMBD, wmma::mem_row_major);
            }
        }
    }
}

// ---------------------------------------------------------------------------
// SIMT fallback GEMMs (round-1 proven). Run only if g_ok == 0.
// ---------------------------------------------------------------------------
__global__ __launch_bounds__(256) void gemm_qkv_simt(const float* __restrict__ A,
                                                     const float* __restrict__ W,
                                                     const float* __restrict__ bias) {
    if (g_ok) return;
    __shared__ float As[16][64];
    __shared__ float Bs[16][64];

    const int bm = blockIdx.y * 64;
    const int bn = blockIdx.x * 64;
    const int tid = threadIdx.x;
    const int tx = tid % 16;
    const int ty = tid / 16;
    const int a_row = tid / 4;
    const int a_k4  = (tid % 4) * 4;
    const int b_row = tid / 16;
    const int b_col = (tid % 16) * 4;

    float acc[4][4] = {};
    for (int k0 = 0; k0 < KDIM; k0 += 16) {
        float4 av = *(const float4*)&A[(size_t)(bm + a_row) * KDIM + k0 + a_k4];
        As[a_k4 + 0][a_row] = av.x;
        As[a_k4 + 1][a_row] = av.y;
        As[a_k4 + 2][a_row] = av.z;
        As[a_k4 + 3][a_row] = av.w;
        *(float4*)&Bs[b_row][b_col] =
            *(const float4*)&W[(size_t)(k0 + b_row) * N_QKV + bn + b_col];
        __syncthreads();
        #pragma unroll
        for (int k = 0; k < 16; k++) {
            float4 af = *(const float4*)&As[k][ty * 4];
            float4 bf = *(const float4*)&Bs[k][tx * 4];
            acc[0][0] += af.x * bf.x; acc[0][1] += af.x * bf.y; acc[0][2] += af.x * bf.z; acc[0][3] += af.x * bf.w;
            acc[1][0] += af.y * bf.x; acc[1][1] += af.y * bf.y; acc[1][2] += af.y * bf.z; acc[1][3] += af.y * bf.w;
            acc[2][0] += af.z * bf.x; acc[2][1] += af.z * bf.y; acc[2][2] += af.z * bf.z; acc[2][3] += af.z * bf.w;
            acc[3][0] += af.w * bf.x; acc[3][1] += af.w * bf.y; acc[3][2] += af.w * bf.z; acc[3][3] += af.w * bf.w;
        }
        __syncthreads();
    }
    const int which = bn / C_EMBD;
    const int head  = (bn % C_EMBD) / HD;
    float* dst = (which == 0) ? g_q : (which == 1) ? g_k : g_v;
    float4 bv = *(const float4*)&bias[bn + tx * 4];
    #pragma unroll
    for (int i = 0; i < 4; i++) {
        int m = bm + ty * 4 + i;
        int b = m / SEQ, t = m % SEQ;
        float4 o;
        o.x = acc[i][0] + bv.x; o.y = acc[i][1] + bv.y;
        o.z = acc[i][2] + bv.z; o.w = acc[i][3] + bv.w;
        *(float4*)&dst[((size_t)(b * NHEAD + head) * SEQ + t) * HD + tx * 4] = o;
    }
}

__global__ __launch_bounds__(256) void gemm_proj_simt(const float* __restrict__ W,
                                                      const float* __restrict__ bias,
                                                      float* __restrict__ out) {
    if (g_ok) return;
    __shared__ float As[16][64];
    __shared__ float Bs[16][64];

    const int bm = blockIdx.y * 64;
    const int bn = blockIdx.x * 64;
    const int tid = threadIdx.x;
    const int tx = tid % 16;
    const int ty = tid / 16;
    const int a_row = tid / 4;
    const int a_k4  = (tid % 4) * 4;
    const int b_row = tid / 16;
    const int b_col = (tid % 16) * 4;

    float acc[4][4] = {};
    for (int k0 = 0; k0 < KDIM; k0 += 16) {
        float4 av = *(const float4*)&g_y[(size_t)(bm + a_row) * KDIM + k0 + a_k4];
        As[a_k4 + 0][a_row] = av.x;
        As[a_k4 + 1][a_row] = av.y;
        As[a_k4 + 2][a_row] = av.z;
        As[a_k4 + 3][a_row] = av.w;
        *(float4*)&Bs[b_row][b_col] =
            *(const float4*)&W[(size_t)(k0 + b_row) * C_EMBD + bn + b_col];
        __syncthreads();
        #pragma unroll
        for (int k = 0; k < 16; k++) {
            float4 af = *(const float4*)&As[k][ty * 4];
            float4 bf = *(const float4*)&Bs[k][tx * 4];
            acc[0][0] += af.x * bf.x; acc[0][1] += af.x * bf.y; acc[0][2] += af.x * bf.z; acc[0][3] += af.x * bf.w;
            acc[1][0] += af.y * bf.x; acc[1][1] += af.y * bf.y; acc[1][2] += af.y * bf.z; acc[1][3] += af.y * bf.w;
            acc[2][0] += af.z * bf.x; acc[2][1] += af.z * bf.y; acc[2][2] += af.z * bf.z; acc[2][3] += af.z * bf.w;
            acc[3][0] += af.w * bf.x; acc[3][1] += af.w * bf.y; acc[3][2] += af.w * bf.z; acc[3][3] += af.w * bf.w;
        }
        __syncthreads();
    }
    float4 bv = *(const float4*)&bias[bn + tx * 4];
    #pragma unroll
    for (int i = 0; i < 4; i++) {
        int m = bm + ty * 4 + i;
        float4 o;
        o.x = acc[i][0] + bv.x; o.y = acc[i][1] + bv.y;
        o.z = acc[i][2] + bv.z; o.w = acc[i][3] + bv.w;
        *(float4*)&out[(size_t)m * C_EMBD + bn + tx * 4] = o;
    }
}

// ---------------------------------------------------------------------------
// Flash attention, fp32, online softmax (round-1 proven).
// ---------------------------------------------------------------------------
__global__ __launch_bounds__(128, 3) void attn_kernel() {
    const int bh  = blockIdx.y;
    const int qt  = (gridDim.x - 1) - blockIdx.x;
    const int q0  = qt * 128;
    const int tid = threadIdx.x;
    const int qi  = q0 + tid;

    __shared__ float Ks[64][64];
    __shared__ float Vs[64][64];

    const float* qp = &g_q[((size_t)bh * SEQ + qi) * HD];
    float qr[64];
    #pragma unroll
    for (int i = 0; i < 16; i++) {
        float4 v = *(const float4*)&qp[i * 4];
        qr[i * 4 + 0] = v.x; qr[i * 4 + 1] = v.y;
        qr[i * 4 + 2] = v.z; qr[i * 4 + 3] = v.w;
    }

    float mx = -1e30f, l = 0.0f;
    float acc[64];
    #pragma unroll
    for (int dd = 0; dd < 64; dd++) acc[dd] = 0.0f;

    const int ntiles = qt * 2 + 2;
    const int r = tid >> 1;
    const int half = (tid & 1) * 32;

    for (int kb = 0; kb < ntiles; kb++) {
        const int j0 = kb * 64;
        {
            const float* kp = &g_k[((size_t)bh * SEQ + j0 + r) * HD + half];
            const float* vp = &g_v[((size_t)bh * SEQ + j0 + r) * HD + half];
            #pragma unroll
            for (int i = 0; i < 8; i++) {
                *(float4*)&Ks[r][half + i * 4] = *(const float4*)&kp[i * 4];
                *(float4*)&Vs[r][half + i * 4] = *(const float4*)&vp[i * 4];
            }
        }
        __syncthreads();

        int jmax = qi - j0 + 1;
        if (jmax > 64) jmax = 64;
        for (int j = 0; j < jmax; j++) {
            float sdot = 0.0f;
            #pragma unroll
            for (int d4 = 0; d4 < 16; d4++) {
                float4 kv = *(const float4*)&Ks[j][d4 * 4];
                sdot += qr[d4 * 4 + 0] * kv.x + qr[d4 * 4 + 1] * kv.y
                      + qr[d4 * 4 + 2] * kv.z + qr[d4 * 4 + 3] * kv.w;
            }
            sdot *= 0.125f;

            if (sdot > mx) {
                float corr = __expf(mx - sdot);
                l *= corr;
                #pragma unroll
                for (int dd = 0; dd < 64; dd++) acc[dd] *= corr;
                mx = sdot;
            }
            float p = __expf(sdot - mx);
            l += p;
            #pragma unroll
            for (int d4 = 0; d4 < 16; d4++) {
                float4 vv = *(const float4*)&Vs[j][d4 * 4];
                acc[d4 * 4 + 0] += p * vv.x;
                acc[d4 * 4 + 1] += p * vv.y;
                acc[d4 * 4 + 2] += p * vv.z;
                acc[d4 * 4 + 3] += p * vv.w;
            }
        }
        __syncthreads();
    }

    const float inv = 1.0f / l;
    const int b = bh >> 4, h = bh & 15;
    float* yp = &g_y[((size_t)b * SEQ + qi) * C_EMBD + h * HD];
    #pragma unroll
    for (int d4 = 0; d4 < 16; d4++) {
        float4 o;
        o.x = acc[d4 * 4 + 0] * inv;
        o.y = acc[d4 * 4 + 1] * inv;
        o.z = acc[d4 * 4 + 2] * inv;
        o.w = acc[d4 * 4 + 3] * inv;
        *(float4*)&yp[d4 * 4] = o;
    }
}

// ---------------------------------------------------------------------------
extern "C" void kernel_launch(void* const* d_in, const int* in_sizes, int n_in,
                              void* d_out, int out_size) {
    const float* x      = (const float*)d_in[0];
    const float* W_attn = (const float*)d_in[1];
    const float* b_attn = (const float*)d_in[2];
    const float* W_proj = (const float*)d_in[3];
    const float* b_proj = (const float*)d_in[4];
    float* out = (float*)d_out;

    // 1. Canary: is bf16 wmma alive?
    canary_kernel<<<1, 32>>>();

    // 2. Conversions for the tensor path (gated; near-free if flag=0)
    cvt_gate<<<(M_TOT * KDIM / 4 + 255) / 256, 256>>>(x, 0, M_TOT * KDIM / 4);
    cvt_gate<<<(KDIM * N_QKV / 4 + 255) / 256, 256>>>(W_attn, 1, KDIM * N_QKV / 4);
    cvt_gate<<<(KDIM * C_EMBD / 4 + 255) / 256, 256>>>(W_proj, 2, KDIM * C_EMBD / 4);

    // 3. QKV GEMM: both variants launched, exactly one does work
    gemm_wmma<0><<<dim3(N_QKV / 128, M_TOT / 128), 256>>>(nullptr, b_attn);
    gemm_qkv_simt<<<dim3(N_QKV / 64, M_TOT / 64), 256>>>(x, W_attn, b_attn);

    // 4. Attention (always)
    attn_kernel<<<dim3(SEQ / 128, BATCH * NHEAD), 128>>>();

    // 5. Projection GEMM: convert y (gated), then both variants
    cvt_gate<<<(M_TOT * KDIM / 4 + 255) / 256, 256>>>(nullptr, 3, M_TOT * KDIM / 4);
    gemm_wmma<1><<<dim3(C_EMBD / 128, M_TOT / 128), 256>>>(out, b_proj);
    gemm_proj_simt<<<dim3(C_EMBD / 64, M_TOT / 64), 256>>>(W_proj, b_proj, out);
}